// round 9
// baseline (speedup 1.0000x reference)
#include <cuda_runtime.h>
#include <math.h>

#define B_   16
#define T_   128
#define I_   256
#define H_   256
#define NZ_  1024          // 4*H
#define NBLK 128           // persistent blocks (<= 148 SMs -> all co-resident)

typedef unsigned long long ull;

// Scratch (static device globals: no allocation)
__device__ float    g_xz[T_ * NZ_ * B_];   // [t][n][b]  8 MB
__device__ float    g_h[2][B_ * H_];       // ping-pong hidden state
__device__ unsigned g_arrive[T_];          // per-step arrival counters

// fast transcendentals: ex2.approx + rcp.approx (~1e-6 rel err each)
__device__ __forceinline__ float fsigmoid(float x) {
    float e; asm("ex2.approx.ftz.f32 %0, %1;" : "=f"(e) : "f"(-1.4426950408889634f * x));
    float r; asm("rcp.approx.ftz.f32 %0, %1;" : "=f"(r) : "f"(1.0f + e));
    return r;
}
__device__ __forceinline__ float ftanh_(float x) {
    x = fminf(fmaxf(x, -30.0f), 30.0f);
    float e; asm("ex2.approx.ftz.f32 %0, %1;" : "=f"(e) : "f"(2.8853900817779268f * x));
    float r; asm("rcp.approx.ftz.f32 %0, %1;" : "=f"(r) : "f"(e + 1.0f));
    return (e - 1.0f) * r;
}

// packed f32x2 helpers (sm_100+)
__device__ __forceinline__ ull pack2(float lo, float hi) {
    ull r; asm("mov.b64 %0, {%1,%2};" : "=l"(r) : "f"(lo), "f"(hi)); return r;
}
__device__ __forceinline__ void unpack2(ull v, float& lo, float& hi) {
    asm("mov.b64 {%0,%1}, %2;" : "=f"(lo), "=f"(hi) : "l"(v));
}
__device__ __forceinline__ ull fma2(ull a, ull b, ull c) {
    ull d; asm("fma.rn.f32x2 %0, %1, %2, %3;" : "=l"(d) : "l"(a), "l"(b), "l"(c));
    return d;
}

// ---------------------------------------------------------------------------
// Kernel 1: XZ[t][n][b] = sum_k x[b][t][k] * Wih[k][n]   (k < 256 rows of Wih)
// grid (8 n-blocks of 128 cols, 128 t), 128 threads
// Also resets the arrival counters (graph-replay safe: runs before kernel 2).
// ---------------------------------------------------------------------------
__global__ void __launch_bounds__(128)
xz_kernel(const float* __restrict__ x, const float* __restrict__ Wih)
{
    if (blockIdx.x == 0 && blockIdx.y == 0 && threadIdx.x < T_)
        g_arrive[threadIdx.x] = 0u;

    __shared__ float x_s[I_ * B_];     // [k][b], 16 KB
    __shared__ float w_s[16 * 128];    // one 16-row k-panel of Wih cols n0..n0+127

    const int t   = blockIdx.y;
    const int n0  = blockIdx.x * 128;
    const int tid = threadIdx.x;

    // stage x[:, t, :] transposed -> x_s[k][b] (coalesced global reads)
    for (int idx = tid; idx < B_ * I_; idx += 128) {
        int b = idx >> 8;
        int k = idx & 255;
        x_s[k * B_ + b] = x[(b * T_ + t) * I_ + k];
    }

    const int bq = tid >> 5;       // 0..3  -> b tile of 4
    const int ng = tid & 31;       // 0..31 -> n tile of 4
    const int b0 = bq * 4;
    const int nn = ng * 4;

    float acc[4][4];
    #pragma unroll
    for (int i = 0; i < 4; i++)
        #pragma unroll
        for (int j = 0; j < 4; j++) acc[i][j] = 0.f;

    for (int kb = 0; kb < 16; kb++) {
        __syncthreads();   // protects x_s fill (1st iter) and w_s reuse
        for (int q = tid; q < 512; q += 128) {
            int r  = q >> 5;
            int c4 = q & 31;
            ((float4*)w_s)[q] =
                ((const float4*)(Wih + (size_t)(kb * 16 + r) * NZ_ + n0))[c4];
        }
        __syncthreads();
        #pragma unroll
        for (int kk = 0; kk < 16; kk++) {
            float4 xv = *(const float4*)&x_s[(kb * 16 + kk) * B_ + b0];
            float4 wv = *(const float4*)&w_s[kk * 128 + nn];
            float xr[4] = {xv.x, xv.y, xv.z, xv.w};
            float wr_[4] = {wv.x, wv.y, wv.z, wv.w};
            #pragma unroll
            for (int i = 0; i < 4; i++)
                #pragma unroll
                for (int j = 0; j < 4; j++)
                    acc[i][j] += xr[i] * wr_[j];
        }
    }

    #pragma unroll
    for (int j = 0; j < 4; j++) {
        float4 o = make_float4(acc[0][j], acc[1][j], acc[2][j], acc[3][j]);
        *(float4*)&g_xz[(size_t)(t * NZ_ + n0 + nn + j) * B_ + b0] = o;
    }
}

// ---------------------------------------------------------------------------
// Kernel 2: persistent recurrence. 128 blocks x 256 threads.
// Warp-dataflow schedule: NO __syncthreads in the main loop.
//  - tid0 polls the global counter (ld.acquire), releases the block via a
//    volatile smem word; warps wake with an LDS spin (~30 cyc).
//  - each warp stages ONLY the 4 h rows its gemm reads (cg-partner warps
//    duplicate identical values -> benign), then __syncwarp -> gemm.
//  - warps 1-7: bar.arrive(1,256) after gemm and run ahead to the next wait;
//    warp 0: bar.sync(1,256), epilogue, publish h, release-red. All cross-
//    warp WAR hazards (d_s, h_s, g_h ping-pong) are ordered through the
//    release-red -> acquire-poll chain.
// ---------------------------------------------------------------------------
__global__ void __launch_bounds__(256)
rec_kernel(const float* __restrict__ h_init, const float* __restrict__ c_init,
           const float* __restrict__ out0,
           const float* __restrict__ Wih,  const float* __restrict__ Whh,
           const float* __restrict__ b_ih, const float* __restrict__ b_hh,
           float* __restrict__ dout)
{
    __shared__ float h_s[B_ * H_];          // 16 KB staged h
    __shared__ float d_s[2][2][4][16];      // [unit][cs(0=Wh,1=Wa)][gate][b]
    __shared__ float A_s[2][4][16];         // running atten@Wa per unit/gate/b
    __shared__ float c_s[2][16];
    __shared__ float att_s[2][16];
    __shared__ float bias_s[2][4];
    __shared__ volatile int s_ready;        // latest globally-ready step

    const int tid  = threadIdx.x;
    const int bid  = blockIdx.x;
    const int w    = tid >> 5;
    const int lane = tid & 31;
    const int bg   = w & 3;        // b tile: b = 4*bg + i
    const int cg   = w >> 2;       // unit index within block (0/1)
    const int unit = bid * 2 + cg;
    const int cs   = lane >> 4;    // 0 -> Whh, 1 -> Wa (Wih rows 256..511)
    const int kc   = lane & 15;    // k-pair base = 32*j' + 2*kc

    // packed weight slice in registers: wr2[c][j'] = {W[k0][n], W[k0+1][n]}
    ull wr2[4][8];
    #pragma unroll
    for (int c = 0; c < 4; c++) {
        const int n = unit + 256 * c;
        #pragma unroll
        for (int j = 0; j < 8; j++) {
            const int k0 = 32 * j + 2 * kc;
            float w0 = cs ? Wih[(size_t)(256 + k0) * NZ_ + n]
                          : Whh[(size_t)k0 * NZ_ + n];
            float w1 = cs ? Wih[(size_t)(256 + k0 + 1) * NZ_ + n]
                          : Whh[(size_t)(k0 + 1) * NZ_ + n];
            wr2[c][j] = pack2(w0, w1);
        }
    }

    if (tid == 0) s_ready = 0;
    if (tid < 8) {
        int ug = tid >> 2, c = tid & 3;
        int n = (bid * 2 + ug) + 256 * c;
        bias_s[ug][c] = b_ih[n] + b_hh[n];
    }
    if (tid < 32) {
        int b = tid & 15, ug = tid >> 4;
        int u = bid * 2 + ug;
        c_s[ug][b]   = c_init[b * H_ + u];
        att_s[ug][b] = out0[b * H_ + u];   // atten includes buf[0] = out0
    }

    // per-warp h staging: only the 4 rows (4bg..4bg+3) this warp's gemm reads
    auto stage_rows = [&](const float* hsrc) {
        const float4* s4 = (const float4*)hsrc + bg * 256;
        float4* d4 = (float4*)h_s + bg * 256;
        float4 r[8];
        #pragma unroll
        for (int q = 0; q < 8; q++) r[q] = __ldcg(&s4[lane + 32 * q]);
        #pragma unroll
        for (int q = 0; q < 8; q++) d4[lane + 32 * q] = r[q];
    };

    auto do_gemm = [&]() {
        ull acc2[4][4];
        #pragma unroll
        for (int i = 0; i < 4; i++)
            #pragma unroll
            for (int c = 0; c < 4; c++) acc2[i][c] = pack2(0.f, 0.f);
        #pragma unroll
        for (int j = 0; j < 8; j++) {
            const int k0 = 32 * j + 2 * kc;
            ull h0 = *(const ull*)&h_s[(4 * bg + 0) * H_ + k0];
            ull h1 = *(const ull*)&h_s[(4 * bg + 1) * H_ + k0];
            ull h2 = *(const ull*)&h_s[(4 * bg + 2) * H_ + k0];
            ull h3 = *(const ull*)&h_s[(4 * bg + 3) * H_ + k0];
            #pragma unroll
            for (int c = 0; c < 4; c++) {
                ull wv = wr2[c][j];
                acc2[0][c] = fma2(h0, wv, acc2[0][c]);
                acc2[1][c] = fma2(h1, wv, acc2[1][c]);
                acc2[2][c] = fma2(h2, wv, acc2[2][c]);
                acc2[3][c] = fma2(h3, wv, acc2[3][c]);
            }
        }
        float acc[4][4];
        #pragma unroll
        for (int i = 0; i < 4; i++)
            #pragma unroll
            for (int c = 0; c < 4; c++) {
                float lo, hi; unpack2(acc2[i][c], lo, hi);
                acc[i][c] = lo + hi;
            }
        // butterfly-allreduce over the 16 kc lanes (stays within cs halves)
        #pragma unroll
        for (int off = 8; off >= 1; off >>= 1)
            #pragma unroll
            for (int i = 0; i < 4; i++)
                #pragma unroll
                for (int c = 0; c < 4; c++)
                    acc[i][c] += __shfl_xor_sync(0xffffffffu, acc[i][c], off);
        if (kc == 0) {
            #pragma unroll
            for (int i = 0; i < 4; i++)
                #pragma unroll
                for (int c = 0; c < 4; c++)
                    d_s[cg][cs][c][4 * bg + i] = acc[i][c];
        }
    };

    // ---- prestep: A_0 = out0 @ Wa  (out0 excluded from h recurrence) ----
    stage_rows(out0);
    __syncwarp();
    do_gemm();
    __syncthreads();
    if (tid < 32) {
        int b = tid & 15, ug = tid >> 4;
        #pragma unroll
        for (int c = 0; c < 4; c++) A_s[ug][c][b] = d_s[ug][1][c][b];
    }
    __syncthreads();   // d_s WAR guard before t=0 gemm; h_s guard for t=0 stage

    // ---- main sequential loop (no __syncthreads inside) ----
    for (int t = 0; t < T_; t++) {
        // warp 0 prefetches this step's xz early (consumed in epilogue)
        float xzv[4];
        const int b  = tid & 15;
        const int ug = tid >> 4;
        if (tid < 32) {
            #pragma unroll
            for (int c = 0; c < 4; c++)
                xzv[c] = __ldcg(&g_xz[(size_t)(t * NZ_ + (bid * 2 + ug) + 256 * c) * B_ + b]);
        }

        // wait for global step t-1 completion
        if (t > 0) {
            if (w == 0) {
                if (lane == 0) {
                    const unsigned* ctr = &g_arrive[t - 1];
                    unsigned v;
                    do {
                        asm volatile("ld.acquire.gpu.global.u32 %0, [%1];"
                                     : "=r"(v) : "l"(ctr) : "memory");
                    } while (v < NBLK);
                    s_ready = t;            // release the other warps (smem)
                }
                __syncwarp();
            } else {
                if (lane == 0) { while (s_ready < t) { } }
                __syncwarp();
            }
        }

        stage_rows(t == 0 ? h_init : g_h[(t - 1) & 1]);
        __syncwarp();
        do_gemm();

        if (w == 0) {
            asm volatile("bar.sync 1, 256;" ::: "memory");   // collect all d_s
            const int u = bid * 2 + ug;
            float z[4];
            #pragma unroll
            for (int c = 0; c < 4; c++) {
                float Av = A_s[ug][c][b];
                if (t > 0) Av += d_s[ug][1][c][b];   // A_t = A_{t-1} + h_{t-1}@Wa
                A_s[ug][c][b] = Av;
                z[c] = xzv[c] + Av + d_s[ug][0][c][b] + bias_s[ug][c];
            }
            float si = fsigmoid(z[0]);
            float sf = fsigmoid(z[1]);
            float tg = ftanh_(z[2]);
            float so = fsigmoid(z[3]);
            float cn = sf * c_s[ug][b] + si * tg;
            float hn = so * ftanh_(cn);
            // publish + release FIRST (critical path), bookkeeping after
            if (t < T_ - 1) {
                __stcg(&g_h[t & 1][b * H_ + u], hn);
                __syncwarp();
                if (tid == 0) {
                    asm volatile("red.release.gpu.global.add.u32 [%0], %1;"
                                 :: "l"(&g_arrive[t]), "r"(1u) : "memory");
                }
            }
            c_s[ug][b] = cn;
            if (t < T_ - 1) att_s[ug][b] += hn;      // attens[-1] sums t<=T-2
            if (t == T_ - 2) {
                dout[3 * 4096 + b * H_ + u] = hn;    // h_prevs[-1]
                dout[4 * 4096 + b * H_ + u] = cn;    // c_prevs[-1]
            }
            if (t == T_ - 1) {
                dout[0 * 4096 + b * H_ + u] = hn;    // out_f (B,1,H)
                dout[1 * 4096 + b * H_ + u] = hn;    // h_f   (1,B,H)
                dout[2 * 4096 + b * H_ + u] = cn;    // c_f   (1,B,H)
            }
        } else {
            asm volatile("bar.arrive 1, 256;" ::: "memory"); // non-blocking
        }
    }

    if (tid < 32) {
        int b = tid & 15, ug = tid >> 4;
        int u = bid * 2 + ug;
        dout[5 * 4096 + b * H_ + u] = att_s[ug][b];  // attens[-1]
    }
}

// ---------------------------------------------------------------------------
// inputs (metadata order): x, hidden_state, cell_state, out, Wih, Whh,
// b_ih, b_hh, W1, b1, W2, b2, W3, b3, bsize, time_step
// W1..b3 are dead (softmax over singleton axis makes weights == 1).
// ---------------------------------------------------------------------------
extern "C" void kernel_launch(void* const* d_in, const int* in_sizes, int n_in,
                              void* d_out, int out_size)
{
    const float* x       = (const float*)d_in[0];
    const float* h_init  = (const float*)d_in[1];
    const float* c_init  = (const float*)d_in[2];
    const float* out0    = (const float*)d_in[3];
    const float* Wih     = (const float*)d_in[4];
    const float* Whh     = (const float*)d_in[5];
    const float* b_ih    = (const float*)d_in[6];
    const float* b_hh    = (const float*)d_in[7];
    float* dout = (float*)d_out;

    dim3 g1(8, T_);
    xz_kernel<<<g1, 128>>>(x, Wih);
    rec_kernel<<<NBLK, 256>>>(h_init, c_init, out0, Wih, Whh, b_ih, b_hh, dout);
}

// round 10
// speedup vs baseline: 1.1744x; 1.1744x over previous
#include <cuda_runtime.h>
#include <math.h>

#define B_   16
#define T_   128
#define I_   256
#define H_   256
#define NZ_  1024          // 4*H
#define NBLK 128           // 4 groups x 32 blocks
#define GRPB 32            // blocks per group (arrivals per step)

typedef unsigned long long ull;

// Scratch (static device globals: no allocation)
__device__ float    g_xz[T_ * NZ_ * B_];   // [t][n][b]  8 MB
__device__ float    g_h[2][B_ * H_];       // ping-pong hidden state [b][u]
__device__ unsigned g_arr[4 * T_ * 8];     // per-(group,step) counters, 32B apart

// fast transcendentals: ex2.approx + rcp.approx (~1e-6 rel err each)
__device__ __forceinline__ float fsigmoid(float x) {
    float e; asm("ex2.approx.ftz.f32 %0, %1;" : "=f"(e) : "f"(-1.4426950408889634f * x));
    float r; asm("rcp.approx.ftz.f32 %0, %1;" : "=f"(r) : "f"(1.0f + e));
    return r;
}
__device__ __forceinline__ float ftanh_(float x) {
    x = fminf(fmaxf(x, -30.0f), 30.0f);
    float e; asm("ex2.approx.ftz.f32 %0, %1;" : "=f"(e) : "f"(2.8853900817779268f * x));
    float r; asm("rcp.approx.ftz.f32 %0, %1;" : "=f"(r) : "f"(e + 1.0f));
    return (e - 1.0f) * r;
}

// packed f32x2 helpers (sm_100+)
__device__ __forceinline__ ull pack2(float lo, float hi) {
    ull r; asm("mov.b64 %0, {%1,%2};" : "=l"(r) : "f"(lo), "f"(hi)); return r;
}
__device__ __forceinline__ void unpack2(ull v, float& lo, float& hi) {
    asm("mov.b64 {%0,%1}, %2;" : "=f"(lo), "=f"(hi) : "l"(v));
}
__device__ __forceinline__ ull fma2(ull a, ull b, ull c) {
    ull d; asm("fma.rn.f32x2 %0, %1, %2, %3;" : "=l"(d) : "l"(a), "l"(b), "l"(c));
    return d;
}

// ---------------------------------------------------------------------------
// Kernel 1: XZ[t][n][b] = sum_k x[b][t][k] * Wih[k][n]   (k < 256 rows of Wih)
// grid (8 n-blocks of 128 cols, 128 t), 128 threads
// Also resets the group counters (graph-replay safe: runs before kernel 2).
// ---------------------------------------------------------------------------
__global__ void __launch_bounds__(128)
xz_kernel(const float* __restrict__ x, const float* __restrict__ Wih)
{
    if (blockIdx.y == 0) {
        int base = (blockIdx.x * 128 + threadIdx.x) * 4;   // 1024 thr x 4 = 4096
        #pragma unroll
        for (int i = 0; i < 4; i++) g_arr[base + i] = 0u;
    }

    __shared__ float x_s[I_ * B_];     // [k][b], 16 KB
    __shared__ float w_s[16 * 128];    // one 16-row k-panel of Wih cols n0..n0+127

    const int t   = blockIdx.y;
    const int n0  = blockIdx.x * 128;
    const int tid = threadIdx.x;

    for (int idx = tid; idx < B_ * I_; idx += 128) {
        int b = idx >> 8;
        int k = idx & 255;
        x_s[k * B_ + b] = x[(b * T_ + t) * I_ + k];
    }

    const int bq = tid >> 5;       // 0..3  -> b tile of 4
    const int ng = tid & 31;       // 0..31 -> n tile of 4
    const int b0 = bq * 4;
    const int nn = ng * 4;

    float acc[4][4];
    #pragma unroll
    for (int i = 0; i < 4; i++)
        #pragma unroll
        for (int j = 0; j < 4; j++) acc[i][j] = 0.f;

    for (int kb = 0; kb < 16; kb++) {
        __syncthreads();
        for (int q = tid; q < 512; q += 128) {
            int r  = q >> 5;
            int c4 = q & 31;
            ((float4*)w_s)[q] =
                ((const float4*)(Wih + (size_t)(kb * 16 + r) * NZ_ + n0))[c4];
        }
        __syncthreads();
        #pragma unroll
        for (int kk = 0; kk < 16; kk++) {
            float4 xv = *(const float4*)&x_s[(kb * 16 + kk) * B_ + b0];
            float4 wv = *(const float4*)&w_s[kk * 128 + nn];
            float xr[4] = {xv.x, xv.y, xv.z, xv.w};
            float wr_[4] = {wv.x, wv.y, wv.z, wv.w};
            #pragma unroll
            for (int i = 0; i < 4; i++)
                #pragma unroll
                for (int j = 0; j < 4; j++)
                    acc[i][j] += xr[i] * wr_[j];
        }
    }

    #pragma unroll
    for (int j = 0; j < 4; j++) {
        float4 o = make_float4(acc[0][j], acc[1][j], acc[2][j], acc[3][j]);
        *(float4*)&g_xz[(size_t)(t * NZ_ + n0 + nn + j) * B_ + b0] = o;
    }
}

// ---------------------------------------------------------------------------
// Kernel 2: persistent recurrence, batch-partitioned into 4 INDEPENDENT
// groups of 32 blocks (the recurrence is batch-separable). Group g owns
// batches 4g..4g+3; block r within the group owns units 8r..8r+7.
// Sync = per-group acquire/release counter (32 arrivals), round-8 skeleton.
// ---------------------------------------------------------------------------
__global__ void __launch_bounds__(256)
rec_kernel(const float* __restrict__ h_init, const float* __restrict__ c_init,
           const float* __restrict__ out0,
           const float* __restrict__ Wih,  const float* __restrict__ Whh,
           const float* __restrict__ b_ih, const float* __restrict__ b_hh,
           float* __restrict__ dout)
{
    __shared__ float h_s[4 * H_];           // 4 KB: the group's 4 batches
    __shared__ float d_s[8][2][4][4];       // [unit][mat][gate][batch]
    __shared__ float A_s[8][4][4];          // running atten@Wa
    __shared__ float c_s[8][4];
    __shared__ float att_s[8][4];
    __shared__ float bias_s[8][4];

    const int tid  = threadIdx.x;
    const int bid  = blockIdx.x;
    const int g    = bid >> 5;     // group 0..3 -> batches 4g..4g+3
    const int r    = bid & 31;     // unit block -> units 8r..8r+7
    const int u0   = r * 8;
    const int b0   = g * 4;
    const int w    = tid >> 5;     // warp = local unit lu (0..7)
    const int lane = tid & 31;
    const int cs   = lane >> 4;    // 0 -> Whh, 1 -> Wa (Wih rows 256..511)
    const int kc   = lane & 15;    // k-pair base = 32*j + 2*kc

    // packed weight slice in registers: wr2[c][j] = {W[k0][n], W[k0+1][n]}
    ull wr2[4][8];
    #pragma unroll
    for (int c = 0; c < 4; c++) {
        const int n = u0 + w + 256 * c;
        #pragma unroll
        for (int j = 0; j < 8; j++) {
            const int k0 = 32 * j + 2 * kc;
            float w0 = cs ? Wih[(size_t)(256 + k0) * NZ_ + n]
                          : Whh[(size_t)k0 * NZ_ + n];
            float w1 = cs ? Wih[(size_t)(256 + k0 + 1) * NZ_ + n]
                          : Whh[(size_t)(k0 + 1) * NZ_ + n];
            wr2[c][j] = pack2(w0, w1);
        }
    }

    if (tid < 32) {
        int lu = tid >> 2, c = tid & 3;          // bias per (unit, gate)
        bias_s[lu][c] = b_ih[u0 + lu + 256 * c] + b_hh[u0 + lu + 256 * c];
    }
    if (tid < 32) {
        int lu = tid >> 2, bl = tid & 3;
        int b = b0 + bl, u = u0 + lu;
        c_s[lu][bl]   = c_init[b * H_ + u];
        att_s[lu][bl] = out0[b * H_ + u];        // atten includes buf[0] = out0
    }

    auto do_gemm = [&]() {
        ull acc2[4][4];                          // [batch][gate]
        #pragma unroll
        for (int i = 0; i < 4; i++)
            #pragma unroll
            for (int c = 0; c < 4; c++) acc2[i][c] = pack2(0.f, 0.f);
        #pragma unroll
        for (int j = 0; j < 8; j++) {
            const int k0 = 32 * j + 2 * kc;
            ull h0 = *(const ull*)&h_s[0 * H_ + k0];
            ull h1 = *(const ull*)&h_s[1 * H_ + k0];
            ull h2 = *(const ull*)&h_s[2 * H_ + k0];
            ull h3 = *(const ull*)&h_s[3 * H_ + k0];
            #pragma unroll
            for (int c = 0; c < 4; c++) {
                ull wv = wr2[c][j];
                acc2[0][c] = fma2(h0, wv, acc2[0][c]);
                acc2[1][c] = fma2(h1, wv, acc2[1][c]);
                acc2[2][c] = fma2(h2, wv, acc2[2][c]);
                acc2[3][c] = fma2(h3, wv, acc2[3][c]);
            }
        }
        float acc[4][4];
        #pragma unroll
        for (int i = 0; i < 4; i++)
            #pragma unroll
            for (int c = 0; c < 4; c++) {
                float lo, hi; unpack2(acc2[i][c], lo, hi);
                acc[i][c] = lo + hi;
            }
        // butterfly-allreduce over the 16 kc lanes (stays within cs halves)
        #pragma unroll
        for (int off = 8; off >= 1; off >>= 1)
            #pragma unroll
            for (int i = 0; i < 4; i++)
                #pragma unroll
                for (int c = 0; c < 4; c++)
                    acc[i][c] += __shfl_xor_sync(0xffffffffu, acc[i][c], off);
        if (kc == 0) {
            #pragma unroll
            for (int i = 0; i < 4; i++)
                #pragma unroll
                for (int c = 0; c < 4; c++)
                    d_s[w][cs][c][i] = acc[i][c];
        }
    };

    // ---- prestep: A_0 = out0 @ Wa  (out0 excluded from h recurrence) ----
    if (tid < 256) {   // stage out0 slice for the group's 4 batches (4 KB)
        *(float4*)&h_s[tid * 4] = *(const float4*)&out0[b0 * H_ + tid * 4];
    }
    __syncthreads();
    do_gemm();
    __syncthreads();
    if (tid < 32) {
        int lu = tid >> 2, bl = tid & 3;
        #pragma unroll
        for (int c = 0; c < 4; c++) A_s[lu][c][bl] = d_s[lu][1][c][bl];
    }

    // ---- main sequential loop (round-8 skeleton, group-local sync) ----
    for (int t = 0; t < T_; t++) {
        // warp 0 prefetches this step's xz early (overlaps the wait)
        float xzv[4];
        const int lu = (tid & 31) >> 2;
        const int bl = tid & 3;
        if (tid < 32) {
            #pragma unroll
            for (int c = 0; c < 4; c++)
                xzv[c] = __ldcg(&g_xz[(size_t)(t * NZ_ + (u0 + lu) + 256 * c) * B_ + (b0 + bl)]);
        }

        // wait: all 32 blocks of this group finished step t-1
        if (t > 0 && tid == 0) {
            const unsigned* ctr = &g_arr[(g * T_ + (t - 1)) * 8];
            unsigned v;
            do {
                asm volatile("ld.acquire.gpu.global.u32 %0, [%1];"
                             : "=r"(v) : "l"(ctr) : "memory");
            } while (v < GRPB);
        }
        __syncthreads();   // (A) release + h_s/d_s reuse guard

        // stage h_{t-1} for the group's 4 batches: one float4 per thread
        {
            const float* hsrc = (t == 0) ? (h_init + b0 * H_)
                                         : (&g_h[(t - 1) & 1][b0 * H_]);
            float4 v = __ldcg((const float4*)(hsrc + tid * 4));
            *(float4*)&h_s[tid * 4] = v;
        }
        __syncthreads();   // (B)

        do_gemm();
        __syncthreads();   // (C)

        if (tid < 32) {
            const int u = u0 + lu;
            const int b = b0 + bl;
            float z[4];
            #pragma unroll
            for (int c = 0; c < 4; c++) {
                float Av = A_s[lu][c][bl];
                if (t > 0) Av += d_s[lu][1][c][bl];  // A_t = A_{t-1} + h_{t-1}@Wa
                A_s[lu][c][bl] = Av;
                z[c] = xzv[c] + Av + d_s[lu][0][c][bl] + bias_s[lu][c];
            }
            float si = fsigmoid(z[0]);
            float sf = fsigmoid(z[1]);
            float tg = ftanh_(z[2]);
            float so = fsigmoid(z[3]);
            float cn = sf * c_s[lu][bl] + si * tg;
            float hn = so * ftanh_(cn);
            // publish + release FIRST (critical path), bookkeeping after
            if (t < T_ - 1) {
                __stcg(&g_h[t & 1][b * H_ + u], hn);
                __syncwarp();
                if (tid == 0) {
                    asm volatile("red.release.gpu.global.add.u32 [%0], %1;"
                                 :: "l"(&g_arr[(g * T_ + t) * 8]), "r"(1u)
                                 : "memory");
                }
            }
            c_s[lu][bl] = cn;
            if (t < T_ - 1) att_s[lu][bl] += hn;     // attens[-1] sums t<=T-2
            if (t == T_ - 2) {
                dout[3 * 4096 + b * H_ + u] = hn;    // h_prevs[-1]
                dout[4 * 4096 + b * H_ + u] = cn;    // c_prevs[-1]
            }
            if (t == T_ - 1) {
                dout[0 * 4096 + b * H_ + u] = hn;    // out_f (B,1,H)
                dout[1 * 4096 + b * H_ + u] = hn;    // h_f   (1,B,H)
                dout[2 * 4096 + b * H_ + u] = cn;    // c_f   (1,B,H)
            }
        }
    }

    if (tid < 32) {
        int lu2 = tid >> 2, bl2 = tid & 3;
        dout[5 * 4096 + (b0 + bl2) * H_ + (u0 + lu2)] = att_s[lu2][bl2];
    }
}

// ---------------------------------------------------------------------------
// inputs (metadata order): x, hidden_state, cell_state, out, Wih, Whh,
// b_ih, b_hh, W1, b1, W2, b2, W3, b3, bsize, time_step
// W1..b3 are dead (softmax over singleton axis makes weights == 1).
// ---------------------------------------------------------------------------
extern "C" void kernel_launch(void* const* d_in, const int* in_sizes, int n_in,
                              void* d_out, int out_size)
{
    const float* x       = (const float*)d_in[0];
    const float* h_init  = (const float*)d_in[1];
    const float* c_init  = (const float*)d_in[2];
    const float* out0    = (const float*)d_in[3];
    const float* Wih     = (const float*)d_in[4];
    const float* Whh     = (const float*)d_in[5];
    const float* b_ih    = (const float*)d_in[6];
    const float* b_hh    = (const float*)d_in[7];
    float* dout = (float*)d_out;

    dim3 g1(8, T_);
    xz_kernel<<<g1, 128>>>(x, Wih);
    rec_kernel<<<NBLK, 256>>>(h_init, c_init, out0, Wih, Whh, b_ih, b_hh, dout);
}